// round 9
// baseline (speedup 1.0000x reference)
#include <cuda_runtime.h>
#include <math.h>

// Problem constants
#define BATCH 64
#define SEQ   512
#define HID   1024
#define EMB   256
#define NCHAR 128

// Geometry: 128 persistent CTAs = 4 batch-groups (tb) x 32 j-tiles (tj).
// 512 threads = 16 warps = 4 per SMSP (latency hiding); one phase per step.
#define GRID     128
#define NTHREADS 512
#define BT       16      // batch rows per CTA
#define JT       32      // hidden rows per CTA

#define SW_STRIDE 36     // padded W row stride (words): 4-phase-balanced LDS.128
#define SP_STRIDE 18     // partial row stride (words): 16 b + pad, 8B-aligned

#define SW_FLOATS (HID * SW_STRIDE)            // 36864
#define SP_FLOATS (4 * JT * SP_STRIDE)         // 2304
#define SMEM_BYTES ((SW_FLOATS + SP_FLOATS) * 4)   // 156,672 B

typedef unsigned long long u64;

// packed f32x2 (sm_100+): one SASS FFMA2 = 2 FMAs
#define FMA2(d, a, b)    asm("fma.rn.f32x2 %0, %1, %2, %0;" : "+l"(d) : "l"(a), "l"(b))
#define ADD2(d, a)       asm("add.rn.f32x2 %0, %0, %1;" : "+l"(d) : "l"(a))
#define PACK2(d, lo, hi) asm("mov.b64 %0, {%1, %2};" : "=l"(d) : "f"(lo), "f"(hi))

// Device-global scratch
__device__ float g_U[NCHAR * HID];                        // U = embeddings @ W_ih^T
__device__ __align__(256) float g_hT[2][HID * BATCH];     // ping-pong h, TRANSPOSED [k][b]
__device__ __align__(256) float g_hB[BATCH * HID];        // final h, batch-major
__device__ unsigned g_cnt[4 * 32];                        // 4 group barriers, 128B apart
__device__ unsigned g_sns[4 * 32];                        // sense; ends at 0 (514 phases)

// ---------------------------------------------------------------------------
// 32-CTA group barrier, acquire/release (no MEMBAR.ALL.GPU).
// ---------------------------------------------------------------------------
__device__ __forceinline__ void gbar(unsigned* cnt, unsigned* sns, unsigned s) {
    __syncthreads();
    if (threadIdx.x == 0) {
        unsigned old;
        asm volatile("atom.release.gpu.global.add.u32 %0, [%1], 1;"
                     : "=r"(old) : "l"(cnt) : "memory");
        if (old == 31u) {
            asm volatile("st.relaxed.gpu.global.u32 [%0], 0;" :: "l"(cnt) : "memory");
            asm volatile("st.release.gpu.global.u32 [%0], %1;" :: "l"(sns), "r"(s) : "memory");
        } else {
            unsigned v;
            do {
                asm volatile("ld.acquire.gpu.global.u32 %0, [%1];"
                             : "=r"(v) : "l"(sns) : "memory");
            } while (v != s);
        }
    }
    __syncthreads();
}

// ---------------------------------------------------------------------------
// Kernel 0: U[c][j] = sum_e emb[c][e] * W_ih[j][e]
// ---------------------------------------------------------------------------
__global__ void u_kernel(const float* __restrict__ emb, const float* __restrict__ wih) {
    int gt   = blockIdx.x * blockDim.x + threadIdx.x;
    int warp = gt >> 5;
    int lane = gt & 31;
    int e0   = lane * 8;
    for (int i = 0; i < 32; i++) {
        int o = warp * 32 + i;
        int c = o >> 10;
        int j = o & 1023;
        const float4* ep = (const float4*)(emb + c * EMB + e0);
        const float4* wp = (const float4*)(wih + j * EMB + e0);
        float4 e1 = __ldg(ep),     e2 = __ldg(ep + 1);
        float4 w1 = __ldg(wp),     w2 = __ldg(wp + 1);
        float acc = e1.x*w1.x + e1.y*w1.y + e1.z*w1.z + e1.w*w1.w
                  + e2.x*w2.x + e2.y*w2.y + e2.z*w2.z + e2.w*w2.w;
        acc += __shfl_xor_sync(0xffffffffu, acc, 16);
        acc += __shfl_xor_sync(0xffffffffu, acc, 8);
        acc += __shfl_xor_sync(0xffffffffu, acc, 4);
        acc += __shfl_xor_sync(0xffffffffu, acc, 2);
        acc += __shfl_xor_sync(0xffffffffu, acc, 1);
        if (lane == 0) g_U[c * HID + j] = acc;
    }
}

// ---------------------------------------------------------------------------
// Persistent RNN scan, transposed h, no staging phase.
// Warp w: bq = w&3 (4 batches), kq = w>>2 (k quarter).
// Lane l: jg = l&7 (4 j's), ks = l>>3 (4-way k split); k = kk*16 + kq*4 + ks.
// Per lane per kk: ulonglong2 h load (4 batches, native f32x2 pairs, L2 direct),
// float4 W from SMEM, 4 dup-MOVs, 8 FFMA2. 64 kk -> 512 FFMA2/lane.
// ---------------------------------------------------------------------------
__global__ void __launch_bounds__(NTHREADS, 1) rnn_kernel(
    const int*   __restrict__ tids,
    const float* __restrict__ whh,
    const float* __restrict__ h0,
    const float* __restrict__ wproj,
    const float* __restrict__ bproj,
    float*       __restrict__ out)
{
    extern __shared__ float smem[];
    float* sW = smem;              // [1024][36]  W slice transposed (32 j + pad)
    float* sP = smem + SW_FLOATS;  // [4][32][18] cross-warp partials

    const int tid = threadIdx.x;
    const int cta = blockIdx.x;
    const int tb  = cta >> 5;      // 0..3
    const int tj  = cta & 31;      // 0..31
    const int b0  = tb * BT;
    const int j0  = tj * JT;
    unsigned* cnt = &g_cnt[tb * 32];
    unsigned* sns = &g_sns[tb * 32];

    // one-time: W_hh slice transposed into SMEM (coalesced LDG rows)
    for (int idx = tid; idx < JT * HID; idx += NTHREADS) {
        int jj = idx >> 10;
        int k  = idx & 1023;
        sW[k * SW_STRIDE + jj] = whh[(j0 + jj) * HID + k];
    }
    // one-time: init transposed h ping buffer (this CTA's produced region)
    for (int idx = tid; idx < JT * BT; idx += NTHREADS) {
        int jj = idx >> 4;
        int bb = idx & 15;
        __stcg(&g_hT[0][(j0 + jj) * BATCH + b0 + bb], __ldg(&h0[j0 + jj]));
    }

    unsigned bs = 1;
    gbar(cnt, sns, bs);                          // phase 1 (init visible)

    const int w  = tid >> 5;
    const int l  = tid & 31;
    const int bq = w & 3;          // 4-batch quarter
    const int kq = w >> 2;         // 0..3
    const int jg = l & 7;          // 4 j's
    const int ks = l >> 3;         // 0..3
    const int klane = kq * 4 + ks; // 16 k-slices of 64

    const float* wp0 = sW + klane * SW_STRIDE + jg * 4;
    const int hoff = klane * BATCH + b0 + bq * 4;

    // combine assignment: one thread per (b, j) output
    const int cjj = tid & 31;
    const int cbb = tid >> 5;

    for (int s = 0; s < SEQ; s++) {
        const int cur = s & 1;
        const int nxt = cur ^ 1;

        // prefetch epilogue operands (independent of h) under compute
        const int   c = __ldg(&tids[(b0 + cbb) * SEQ + s]);
        const float u = __ldg(&g_U[c * HID + j0 + cjj]);

        // ---- packed f32x2 partial GEMM: 4b x 4j per lane over 64 k's ----
        u64 acc[2][4];
        #pragma unroll
        for (int bp = 0; bp < 2; bp++)
            #pragma unroll
            for (int jc = 0; jc < 4; jc++) acc[bp][jc] = 0ull;

        const ulonglong2* hp = (const ulonglong2*)(g_hT[cur] + hoff);
        const float* wp = wp0;
        #pragma unroll 8
        for (int kk = 0; kk < 64; kk++) {
            ulonglong2 hv = __ldcg(hp);              // h[b..b+3] as 2 native f32x2
            float4 wv = *(const float4*)wp;
            hp += (16 * BATCH) / 4;                  // +16 k rows (ulonglong2 = 4 floats)
            wp += 16 * SW_STRIDE;

            u64 wd0, wd1, wd2, wd3;
            PACK2(wd0, wv.x, wv.x); PACK2(wd1, wv.y, wv.y);
            PACK2(wd2, wv.z, wv.z); PACK2(wd3, wv.w, wv.w);

            FMA2(acc[0][0], hv.x, wd0); FMA2(acc[0][1], hv.x, wd1);
            FMA2(acc[0][2], hv.x, wd2); FMA2(acc[0][3], hv.x, wd3);
            FMA2(acc[1][0], hv.y, wd0); FMA2(acc[1][1], hv.y, wd1);
            FMA2(acc[1][2], hv.y, wd2); FMA2(acc[1][3], hv.y, wd3);
        }

        // ---- reduce over ks (lane bits 3,4), packed adds ----
        #pragma unroll
        for (int bp = 0; bp < 2; bp++)
            #pragma unroll
            for (int jc = 0; jc < 4; jc++) {
                u64 t;
                t = __shfl_xor_sync(0xffffffffu, acc[bp][jc], 8);  ADD2(acc[bp][jc], t);
                t = __shfl_xor_sync(0xffffffffu, acc[bp][jc], 16); ADD2(acc[bp][jc], t);
            }

        // ---- stash kq partials ----
        if (ks == 0) {
            float* base = sP + (kq * JT + jg * 4) * SP_STRIDE + bq * 4;
            #pragma unroll
            for (int jc = 0; jc < 4; jc++) {
                *(u64*)(base + jc * SP_STRIDE + 0) = acc[0][jc];
                *(u64*)(base + jc * SP_STRIDE + 2) = acc[1][jc];
            }
        }
        __syncthreads();

        // ---- combine 4 k-quarters, add U, tanh, store next h ----
        {
            float sum = sP[(0 * JT + cjj) * SP_STRIDE + cbb]
                      + sP[(1 * JT + cjj) * SP_STRIDE + cbb]
                      + sP[(2 * JT + cjj) * SP_STRIDE + cbb]
                      + sP[(3 * JT + cjj) * SP_STRIDE + cbb];
            float hn = tanhf(sum + u);
            if (s < SEQ - 1)
                __stcg(&g_hT[nxt][(j0 + cjj) * BATCH + b0 + cbb], hn);
            else
                __stcg(&g_hB[(b0 + cbb) * HID + j0 + cjj], hn);  // coalesced final
        }

        bs ^= 1; gbar(cnt, sns, bs);                 // phases 2..513
    }

    // ---- final projection: out[b][c] = h_final[b] . W_proj[c] + b_proj[c] ----
    if (tid < 64) {
        const int bb = tid >> 2;
        const int cc = tid & 3;
        const int b  = b0 + bb;
        const int c  = tj * 4 + cc;
        const float* hp = g_hB + b * HID;
        const float* wp = wproj + c * HID;
        float acc2 = 0.0f;
        #pragma unroll 4
        for (int k = 0; k < HID; k += 4) {
            float4 hv = __ldcg((const float4*)(hp + k));
            float4 wv = *(const float4*)(wp + k);
            acc2 += hv.x*wv.x + hv.y*wv.y + hv.z*wv.z + hv.w*wv.w;
        }
        out[b * NCHAR + c] = acc2 + bproj[c];
    }

    bs ^= 1; gbar(cnt, sns, bs);                     // phase 514 -> sense back to 0
}

// ---------------------------------------------------------------------------
// Launch: graph-capturable, no allocations, no syncs.
// Inputs: t, embeddings, W_ih, W_hh, h0, W_proj, b_proj.
// ---------------------------------------------------------------------------
extern "C" void kernel_launch(void* const* d_in, const int* in_sizes, int n_in,
                              void* d_out, int out_size)
{
    const int*   t     = (const int*)  d_in[0];
    const float* emb   = (const float*)d_in[1];
    const float* wih   = (const float*)d_in[2];
    const float* whh   = (const float*)d_in[3];
    const float* h0    = (const float*)d_in[4];
    const float* wproj = (const float*)d_in[5];
    const float* bproj = (const float*)d_in[6];
    float*       out   = (float*)d_out;

    cudaFuncSetAttribute(rnn_kernel, cudaFuncAttributeMaxDynamicSharedMemorySize, SMEM_BYTES);

    u_kernel<<<512, 256>>>(emb, wih);
    rnn_kernel<<<GRID, NTHREADS, SMEM_BYTES>>>(t, whh, h0, wproj, bproj, out);
}

// round 10
// speedup vs baseline: 1.1984x; 1.1984x over previous
#include <cuda_runtime.h>
#include <math.h>

// Problem constants
#define BATCH 64
#define SEQ   512
#define HID   1024
#define EMB   256
#define NCHAR 128

// Geometry: 128 persistent CTAs = 4 batch-groups (tb) x 32 j-tiles (tj).
// 512 threads = 16 warps = 4 per SMSP.
#define GRID     128
#define NTHREADS 512
#define BT       16      // batch rows per CTA
#define JT       32      // hidden rows per CTA

#define SW_STRIDE 36     // W row stride (words): exactly-balanced 4-wf LDS.128
#define SH_STRIDE 18     // h row stride (words): conflict-free LDS.64 ({0,18,4,22} banks)
#define SP_STRIDE 34     // partial row stride (words); sP ALIASES sH (sync-guarded)

#define SW_FLOATS (HID * SW_STRIDE)            // 36864
#define SH_FLOATS (HID * SH_STRIDE)            // 18432
#define SMEM_BYTES ((SW_FLOATS + SH_FLOATS) * 4)   // 221,184 B

typedef unsigned long long u64;

// packed f32x2 (sm_100+): one SASS FFMA2 = 2 FMAs
#define FMA2(d, a, b)    asm("fma.rn.f32x2 %0, %1, %2, %0;" : "+l"(d) : "l"(a), "l"(b))
#define ADD2(d, a)       asm("add.rn.f32x2 %0, %0, %1;" : "+l"(d) : "l"(a))
#define PACK2(d, lo, hi) asm("mov.b64 %0, {%1, %2};" : "=l"(d) : "f"(lo), "f"(hi))
#define LDS64(d, addr)   asm volatile("ld.shared.b64 %0, [%1];" : "=l"(d) : "r"(addr))
#define STS64(addr, v)   asm volatile("st.shared.b64 [%0], %1;" :: "r"(addr), "l"(v))

// Device-global scratch
__device__ float g_U[NCHAR * HID];           // U = embeddings @ W_ih^T
__device__ float g_h[2][BATCH * HID];        // ping-pong hidden state, batch-major
__device__ unsigned g_count[4 * 32];         // 4 group barrier counters (128B apart)
__device__ volatile unsigned g_sense[4 * 32];// sense; ends at 0 (514 phases/launch)

// ---------------------------------------------------------------------------
// 32-CTA group barrier (threadfence version — from the best-passing run).
// ---------------------------------------------------------------------------
__device__ __forceinline__ void gbar(unsigned* cnt, volatile unsigned* sns, unsigned s) {
    __syncthreads();
    if (threadIdx.x == 0) {
        __threadfence();
        if (atomicAdd(cnt, 1u) == 31u) {
            *cnt = 0;
            __threadfence();
            *sns = s;
        } else {
            while (*sns != s) { }
            __threadfence();
        }
    }
    __syncthreads();
}

// ---------------------------------------------------------------------------
// Kernel 0: U[c][j] = sum_e emb[c][e] * W_ih[j][e]
// ---------------------------------------------------------------------------
__global__ void u_kernel(const float* __restrict__ emb, const float* __restrict__ wih) {
    int gt   = blockIdx.x * blockDim.x + threadIdx.x;
    int warp = gt >> 5;
    int lane = gt & 31;
    int e0   = lane * 8;
    for (int i = 0; i < 32; i++) {
        int o = warp * 32 + i;
        int c = o >> 10;
        int j = o & 1023;
        const float4* ep = (const float4*)(emb + c * EMB + e0);
        const float4* wp = (const float4*)(wih + j * EMB + e0);
        float4 e1 = __ldg(ep),     e2 = __ldg(ep + 1);
        float4 w1 = __ldg(wp),     w2 = __ldg(wp + 1);
        float acc = e1.x*w1.x + e1.y*w1.y + e1.z*w1.z + e1.w*w1.w
                  + e2.x*w2.x + e2.y*w2.y + e2.z*w2.z + e2.w*w2.w;
        acc += __shfl_xor_sync(0xffffffffu, acc, 16);
        acc += __shfl_xor_sync(0xffffffffu, acc, 8);
        acc += __shfl_xor_sync(0xffffffffu, acc, 4);
        acc += __shfl_xor_sync(0xffffffffu, acc, 2);
        acc += __shfl_xor_sync(0xffffffffu, acc, 1);
        if (lane == 0) g_U[c * HID + j] = acc;
    }
}

// ---------------------------------------------------------------------------
// Persistent RNN scan.
// Warp w: bhalf = w&1 (8 batches), kq = w>>1 (k eighth).
// Lane l:  jg = l&7 (4 j's), ks = l>>3; klane = kq*4+ks; k = kk*32 + klane.
// Per lane per kk: 4x LDS.64 h (= 4 native f32x2 pairs, conflict-free),
// 1x LDS.128 W (stride 36, balanced 4-wf), 4 dup MOVs, 16 FFMA2.
// ---------------------------------------------------------------------------
__global__ void __launch_bounds__(NTHREADS, 1) rnn_kernel(
    const int*   __restrict__ tids,
    const float* __restrict__ whh,
    const float* __restrict__ h0,
    const float* __restrict__ wproj,
    const float* __restrict__ bproj,
    float*       __restrict__ out)
{
    extern __shared__ float smem[];
    float* sW = smem;                // [1024][36]  W slice transposed (32 j + pad)
    float* sH = smem + SW_FLOATS;    // [1024][18]  h tile [k][16 b + pad]
    float* sP = sH;                  // [8][16][34] partials — ALIASES sH (sync-guarded)

    const int tid = threadIdx.x;
    const int cta = blockIdx.x;
    const int tb  = cta >> 5;        // 0..3
    const int tj  = cta & 31;        // 0..31
    const int b0  = tb * BT;
    const int j0  = tj * JT;
    unsigned*          cnt = &g_count[tb * 32];
    volatile unsigned* sns = &g_sense[tb * 32];

    // one-time: W_hh slice transposed into SMEM (coalesced LDG rows)
    for (int idx = tid; idx < JT * HID; idx += NTHREADS) {
        int jj = idx >> 10;
        int k  = idx & 1023;
        sW[k * SW_STRIDE + jj] = whh[(j0 + jj) * HID + k];
    }
    // one-time: init h ping buffer (this CTA's 16b x 32j tile)
    for (int idx = tid; idx < BT * JT; idx += NTHREADS) {
        int bb = idx >> 5;
        int jj = idx & 31;
        g_h[0][(b0 + bb) * HID + (j0 + jj)] = h0[j0 + jj];
    }

    unsigned bs = 1;
    gbar(cnt, sns, bs);                          // phase 1 (init visible)

    const int w     = tid >> 5;
    const int l     = tid & 31;
    const int bhalf = w & 1;
    const int kq    = w >> 1;        // 0..7
    const int jg    = l & 7;
    const int ks    = l >> 3;        // 0..3
    const int klane = kq * 4 + ks;   // 0..31

    const unsigned shb = (unsigned)__cvta_generic_to_shared(sH);
    const unsigned ha0 = shb + (unsigned)(klane * SH_STRIDE + bhalf * 8) * 4u;
    const float* wp0 = sW + klane * SW_STRIDE + jg * 4;

    // staging: warp covers 4 k-quads x 8 batch-pairs per iteration
    const int st_bb2 = l & 7;        // batch pair 0..7
    const int st_kq4 = l >> 3;       // k-quad slot 0..3

    // combine: one thread per (b, j) output
    const int cbb = tid >> 5;
    const int cjj = tid & 31;
    const int crow = (cbb >> 3) * 8 + (cjj >> 2);              // bhalf*8 + jg
    const int cword = ((cbb >> 1) & 3) * 8 + (cjj & 3) * 2 + (cbb & 1);

    for (int s = 0; s < SEQ; s++) {
        const int cur = s & 1;
        const int nxt = cur ^ 1;

        // prefetch epilogue operands (hidden under staging + compute)
        const int   c = __ldg(&tids[(b0 + cbb) * SEQ + s]);
        const float u = __ldg(&g_U[c * HID + j0 + cjj]);

        // ---- stage h tile: sH[k][bb] as f32x2 batch-pairs, conflict-free STS.64 ----
        {
            const float* hsrc = g_h[cur] + (b0 + st_bb2 * 2) * HID;
            #pragma unroll
            for (int it = 0; it < 4; it++) {
                int kquad = w * 64 + it * 16 + st_kq4 * 4;
                float4 A = __ldcg((const float4*)(hsrc + kquad));
                float4 B = __ldcg((const float4*)(hsrc + HID + kquad));
                unsigned a = shb + (unsigned)(kquad * SH_STRIDE + st_bb2 * 2) * 4u;
                u64 v;
                PACK2(v, A.x, B.x); STS64(a, v);
                PACK2(v, A.y, B.y); STS64(a + SH_STRIDE * 4, v);
                PACK2(v, A.z, B.z); STS64(a + 2 * SH_STRIDE * 4, v);
                PACK2(v, A.w, B.w); STS64(a + 3 * SH_STRIDE * 4, v);
            }
        }
        __syncthreads();

        // ---- packed f32x2 GEMM: 8b x 4j per lane over 32 k's ----
        u64 acc[4][4];   // [batch-pair][j]
        #pragma unroll
        for (int bp = 0; bp < 4; bp++)
            #pragma unroll
            for (int jc = 0; jc < 4; jc++) acc[bp][jc] = 0ull;

        unsigned ha = ha0;
        const float* wp = wp0;
        #pragma unroll 4
        for (int kk = 0; kk < 32; kk++) {
            u64 hp0, hp1, hp2, hp3;
            LDS64(hp0, ha); LDS64(hp1, ha + 8); LDS64(hp2, ha + 16); LDS64(hp3, ha + 24);
            float4 wv = *(const float4*)wp;
            ha += 32 * SH_STRIDE * 4;
            wp += 32 * SW_STRIDE;

            u64 wd0, wd1, wd2, wd3;
            PACK2(wd0, wv.x, wv.x); PACK2(wd1, wv.y, wv.y);
            PACK2(wd2, wv.z, wv.z); PACK2(wd3, wv.w, wv.w);

            FMA2(acc[0][0], hp0, wd0); FMA2(acc[0][1], hp0, wd1);
            FMA2(acc[0][2], hp0, wd2); FMA2(acc[0][3], hp0, wd3);
            FMA2(acc[1][0], hp1, wd0); FMA2(acc[1][1], hp1, wd1);
            FMA2(acc[1][2], hp1, wd2); FMA2(acc[1][3], hp1, wd3);
            FMA2(acc[2][0], hp2, wd0); FMA2(acc[2][1], hp2, wd1);
            FMA2(acc[2][2], hp2, wd2); FMA2(acc[2][3], hp2, wd3);
            FMA2(acc[3][0], hp3, wd0); FMA2(acc[3][1], hp3, wd1);
            FMA2(acc[3][2], hp3, wd2); FMA2(acc[3][3], hp3, wd3);
        }

        // ---- reduce over ks (lane bits 3,4), packed adds (register-only) ----
        #pragma unroll
        for (int bp = 0; bp < 4; bp++)
            #pragma unroll
            for (int jc = 0; jc < 4; jc++) {
                u64 t;
                t = __shfl_xor_sync(0xffffffffu, acc[bp][jc], 8);  ADD2(acc[bp][jc], t);
                t = __shfl_xor_sync(0xffffffffu, acc[bp][jc], 16); ADD2(acc[bp][jc], t);
            }

        __syncthreads();   // all sH reads done before stash overwrites (sP aliases sH)

        // ---- stash kq partials: row per (kq, bhalf*8+jg) ----
        if (ks == 0) {
            float* row = sP + (kq * 16 + bhalf * 8 + jg) * SP_STRIDE;
            #pragma unroll
            for (int bp = 0; bp < 4; bp++)
                #pragma unroll
                for (int jc = 0; jc < 4; jc++)
                    *(u64*)(row + bp * 8 + jc * 2) = acc[bp][jc];
        }
        __syncthreads();

        // ---- combine 8 k-eighths, add U, tanh, store next h (coalesced) ----
        {
            float sum = 0.0f;
            #pragma unroll
            for (int q = 0; q < 8; q++)
                sum += sP[(q * 16 + crow) * SP_STRIDE + cword];
            float hn = tanhf(sum + u);
            __stcg(&g_h[nxt][(b0 + cbb) * HID + j0 + cjj], hn);
        }

        bs ^= 1; gbar(cnt, sns, bs);                 // phases 2..513
    }

    // ---- final projection: out[b][c] = h_final[b] . W_proj[c] + b_proj[c] ----
    if (tid < 64) {
        const int bb = tid >> 2;
        const int cc = tid & 3;
        const int b  = b0 + bb;
        const int ch = tj * 4 + cc;
        const float* hp = g_h[0] + b * HID;
        const float* wp = wproj + ch * HID;
        float acc2 = 0.0f;
        #pragma unroll 4
        for (int k = 0; k < HID; k += 4) {
            float4 hv = __ldcg((const float4*)(hp + k));
            float4 wv = *(const float4*)(wp + k);
            acc2 += hv.x*wv.x + hv.y*wv.y + hv.z*wv.z + hv.w*wv.w;
        }
        out[b * NCHAR + ch] = acc2 + bproj[ch];
    }

    bs ^= 1; gbar(cnt, sns, bs);                     // phase 514 -> sense back to 0
}

// ---------------------------------------------------------------------------
// Launch: graph-capturable, no allocations, no syncs.
// Inputs: t, embeddings, W_ih, W_hh, h0, W_proj, b_proj.
// ---------------------------------------------------------------------------
extern "C" void kernel_launch(void* const* d_in, const int* in_sizes, int n_in,
                              void* d_out, int out_size)
{
    const int*   t     = (const int*)  d_in[0];
    const float* emb   = (const float*)d_in[1];
    const float* wih   = (const float*)d_in[2];
    const float* whh   = (const float*)d_in[3];
    const float* h0    = (const float*)d_in[4];
    const float* wproj = (const float*)d_in[5];
    const float* bproj = (const float*)d_in[6];
    float*       out   = (float*)d_out;

    cudaFuncSetAttribute(rnn_kernel, cudaFuncAttributeMaxDynamicSharedMemorySize, SMEM_BYTES);

    u_kernel<<<512, 256>>>(emb, wih);
    rnn_kernel<<<GRID, NTHREADS, SMEM_BYTES>>>(t, whh, h0, wproj, bproj, out);
}